// round 2
// baseline (speedup 1.0000x reference)
#include <cuda_runtime.h>
#include <cuda_bf16.h>

#define BQ 8
#define NQ 900
#define CC 256
#define HEADS 8
#define PP 4
#define HD 32
#define BEVH 200
#define BEVW 200
#define RADIUS 0.2f
#define MROWS 10                 // query rows per CTA; 900 = 90 * 10
#define GROUPS (NQ / MROWS)      // 90

__global__ __launch_bounds__(256)
void deform_attn_kernel(
    const float* __restrict__ query,
    const float* __restrict__ memory,
    const float* __restrict__ refp,
    const float* __restrict__ w_off,
    const float* __restrict__ b_off,
    const float* __restrict__ w_wt,
    const float* __restrict__ b_wt,
    const float* __restrict__ w_out,
    const float* __restrict__ b_out,
    float* __restrict__ out)
{
    __shared__ float q_s[MROWS][CC];            // 10 KB
    __shared__ float fused_s[MROWS][CC];        // 10 KB
    __shared__ float proj_s[MROWS][HEADS * PP * 3];  // 96 proj outputs per row: [0,64)=off, [64,96)=wt
    __shared__ float sx[MROWS][HEADS * PP];
    __shared__ float sy[MROWS][HEADS * PP];
    __shared__ float wts[MROWS][HEADS * PP];

    const int bid = blockIdx.x;
    const int b = bid / GROUPS;
    const int g = bid % GROUPS;
    const int n0 = g * MROWS;
    const int t = threadIdx.x;

    // ---- Phase A: load 10 query rows (coalesced) ----
    {
        const float* qbase = query + ((size_t)b * NQ + n0) * CC;
        #pragma unroll
        for (int r = 0; r < MROWS; r++)
            q_s[r][t] = qbase[(size_t)r * CC + t];
    }
    __syncthreads();

    // ---- Phase B: projections. 960 outputs = 10 rows x 96 cols, spread over 256 threads ----
    // col < 64 -> w_off column; col in [64,96) -> w_wt column (col-64)
    {
        #pragma unroll
        for (int i = 0; i < 4; i++) {
            const int o = t + i * 256;
            if (o < MROWS * 96) {
                const int row = o / 96;
                const int col = o % 96;
                float acc;
                if (col < 64) {
                    acc = b_off[col];
                    const float* w = w_off + col;
                    #pragma unroll 4
                    for (int k = 0; k < CC; k++)
                        acc = fmaf(q_s[row][k], w[(size_t)k * 64], acc);
                } else {
                    const int c = col - 64;
                    acc = b_wt[c];
                    const float* w = w_wt + c;
                    #pragma unroll 4
                    for (int k = 0; k < CC; k++)
                        acc = fmaf(q_s[row][k], w[(size_t)k * 32], acc);
                }
                proj_s[row][col] = acc;
            }
        }
    }
    __syncthreads();

    // ---- Phase C: sampling coords (320 pairs) + per-head softmax (80 heads) ----
    {
        #pragma unroll
        for (int i = 0; i < 2; i++) {
            const int o = t + i * 256;
            if (o < MROWS * 32) {
                const int row = o / 32;
                const int pair = o % 32;
                const float rx = refp[((size_t)b * NQ + n0 + row) * 2 + 0];
                const float ry = refp[((size_t)b * NQ + n0 + row) * 2 + 1];
                const float ox = tanhf(proj_s[row][pair * 2 + 0]) * RADIUS;
                const float oy = tanhf(proj_s[row][pair * 2 + 1]) * RADIUS;
                sx[row][pair] = (rx + ox) * (float)BEVW - 0.5f;
                sy[row][pair] = (ry + oy) * (float)BEVH - 0.5f;
            }
        }
        if (t < MROWS * HEADS) {   // 80
            const int row = t >> 3;
            const int h = t & 7;
            const float l0 = proj_s[row][64 + h * 4 + 0];
            const float l1 = proj_s[row][64 + h * 4 + 1];
            const float l2 = proj_s[row][64 + h * 4 + 2];
            const float l3 = proj_s[row][64 + h * 4 + 3];
            const float m = fmaxf(fmaxf(l0, l1), fmaxf(l2, l3));
            const float e0 = __expf(l0 - m);
            const float e1 = __expf(l1 - m);
            const float e2 = __expf(l2 - m);
            const float e3 = __expf(l3 - m);
            const float inv = 1.0f / (e0 + e1 + e2 + e3);
            wts[row][h * 4 + 0] = e0 * inv;
            wts[row][h * 4 + 1] = e1 * inv;
            wts[row][h * 4 + 2] = e2 * inv;
            wts[row][h * 4 + 3] = e3 * inv;
        }
    }
    __syncthreads();

    // ---- Phase D: bilinear gather. thread = (head, channel); loop over rows ----
    {
        const int h = t >> 5;          // 0..7
        const int d = t & 31;          // 0..31
        const float* mb = memory + (size_t)b * (BEVH * BEVW) * CC + h * HD + d;
        #pragma unroll
        for (int r = 0; r < MROWS; r++) {
            float acc = 0.0f;
            #pragma unroll
            for (int p = 0; p < PP; p++) {
                const int pair = h * PP + p;
                const float xx = sx[r][pair];
                const float yy = sy[r][pair];
                const float x0f = floorf(xx);
                const float y0f = floorf(yy);
                const float fx = xx - x0f;
                const float fy = yy - y0f;
                const int x0 = (int)x0f;
                const int y0 = (int)y0f;
                const int x1 = x0 + 1;
                const int y1 = y0 + 1;
                const bool vx0 = (x0 >= 0) & (x0 < BEVW);
                const bool vx1 = (x1 >= 0) & (x1 < BEVW);
                const bool vy0 = (y0 >= 0) & (y0 < BEVH);
                const bool vy1 = (y1 >= 0) & (y1 < BEVH);
                const float v00 = (vx0 && vy0) ? mb[(size_t)(y0 * BEVW + x0) * CC] : 0.0f;
                const float v01 = (vx1 && vy0) ? mb[(size_t)(y0 * BEVW + x1) * CC] : 0.0f;
                const float v10 = (vx0 && vy1) ? mb[(size_t)(y1 * BEVW + x0) * CC] : 0.0f;
                const float v11 = (vx1 && vy1) ? mb[(size_t)(y1 * BEVW + x1) * CC] : 0.0f;
                const float top = v00 * (1.0f - fx) + v01 * fx;
                const float bot = v10 * (1.0f - fx) + v11 * fx;
                acc = fmaf(wts[r][pair], top * (1.0f - fy) + bot * fy, acc);
            }
            fused_s[r][h * HD + d] = acc;
        }
    }
    __syncthreads();

    // ---- Phase E: output projection. thread = column t, all 10 rows; float4 over k ----
    {
        float acc[MROWS];
        const float bo = b_out[t];
        #pragma unroll
        for (int r = 0; r < MROWS; r++) acc[r] = bo;

        const float* w = w_out + t;
        for (int k = 0; k < CC; k += 4) {
            const float w0 = w[(size_t)(k + 0) * CC];
            const float w1 = w[(size_t)(k + 1) * CC];
            const float w2 = w[(size_t)(k + 2) * CC];
            const float w3 = w[(size_t)(k + 3) * CC];
            #pragma unroll
            for (int r = 0; r < MROWS; r++) {
                const float4 f = *reinterpret_cast<const float4*>(&fused_s[r][k]);
                acc[r] = fmaf(f.x, w0, acc[r]);
                acc[r] = fmaf(f.y, w1, acc[r]);
                acc[r] = fmaf(f.z, w2, acc[r]);
                acc[r] = fmaf(f.w, w3, acc[r]);
            }
        }
        float* obase = out + ((size_t)b * NQ + n0) * CC + t;
        #pragma unroll
        for (int r = 0; r < MROWS; r++)
            obase[(size_t)r * CC] = acc[r];
    }
}

extern "C" void kernel_launch(void* const* d_in, const int* in_sizes, int n_in,
                              void* d_out, int out_size) {
    const float* query  = (const float*)d_in[0];
    const float* memory = (const float*)d_in[1];
    const float* refp   = (const float*)d_in[2];
    const float* w_off  = (const float*)d_in[3];
    const float* b_off  = (const float*)d_in[4];
    const float* w_wt   = (const float*)d_in[5];
    const float* b_wt   = (const float*)d_in[6];
    const float* w_out  = (const float*)d_in[7];
    const float* b_out  = (const float*)d_in[8];
    // d_in[9], d_in[10] = bev_h, bev_w (200x200, compiled in)

    float* out = (float*)d_out;
    deform_attn_kernel<<<BQ * GROUPS, 256>>>(query, memory, refp, w_off, b_off,
                                             w_wt, b_wt, w_out, b_out, out);
}

// round 4
// speedup vs baseline: 1.2785x; 1.2785x over previous
#include <cuda_runtime.h>
#include <cuda_bf16.h>

#define BQ 8
#define NQ 900
#define CC 256
#define HEADS 8
#define PP 4
#define HD 32
#define BEVH 200
#define BEVW 200
#define RADIUS 0.2f
#define MROWS 20                 // query rows per CTA; 900 = 45 * 20
#define GROUPS (NQ / MROWS)      // 45
#define RHALF (MROWS / 2)        // 10

__global__ __launch_bounds__(256)
void deform_attn_kernel(
    const float* __restrict__ query,
    const float* __restrict__ memory,
    const float* __restrict__ refp,
    const float* __restrict__ w_off,
    const float* __restrict__ b_off,
    const float* __restrict__ w_wt,
    const float* __restrict__ b_wt,
    const float* __restrict__ w_out,
    const float* __restrict__ b_out,
    float* __restrict__ out)
{
    // q_s and fused_s share one buffer: q_s is dead after Phase B; fused_s is
    // first written in Phase D (syncthreads separates the phases).
    __shared__ float buf_s[MROWS][CC];               // 20 KB (query, then fused)
    __shared__ float proj_s[MROWS][HEADS * PP * 3];  // [0,64)=off, [64,96)=wt : 7.5 KB
    __shared__ float sx[MROWS][HEADS * PP];          // 2.5 KB
    __shared__ float sy[MROWS][HEADS * PP];          // 2.5 KB
    __shared__ float wts[MROWS][HEADS * PP];         // 2.5 KB

    const int bid = blockIdx.x;
    const int b = bid / GROUPS;
    const int g = bid % GROUPS;
    const int n0 = g * MROWS;
    const int t = threadIdx.x;

    // ---- Phase A: load MROWS query rows (coalesced) ----
    {
        const float* qbase = query + ((size_t)b * NQ + n0) * CC;
        #pragma unroll
        for (int r = 0; r < MROWS; r++)
            buf_s[r][t] = qbase[(size_t)r * CC + t];
    }
    __syncthreads();

    // ---- Phase B: projections. thread = (col, row-half). 192 active threads.
    //      col < 64 -> w_off column; col in [64,96) -> w_wt column.
    //      Each thread accumulates RHALF=10 rows -> weights read 2x per CTA.
    if (t < 192) {
        const int col = t % 96;
        const int r0 = (t / 96) * RHALF;
        const float* w;
        int ld;
        float bias;
        if (col < 64) { w = w_off + col; ld = 64; bias = b_off[col]; }
        else          { w = w_wt + (col - 64); ld = 32; bias = b_wt[col - 64]; }

        float acc[RHALF];
        #pragma unroll
        for (int r = 0; r < RHALF; r++) acc[r] = bias;

        for (int k = 0; k < CC; k += 4) {
            const float w0 = w[(size_t)(k + 0) * ld];
            const float w1 = w[(size_t)(k + 1) * ld];
            const float w2 = w[(size_t)(k + 2) * ld];
            const float w3 = w[(size_t)(k + 3) * ld];
            #pragma unroll
            for (int r = 0; r < RHALF; r++) {
                const float4 q = *reinterpret_cast<const float4*>(&buf_s[r0 + r][k]);
                acc[r] = fmaf(q.x, w0, acc[r]);
                acc[r] = fmaf(q.y, w1, acc[r]);
                acc[r] = fmaf(q.z, w2, acc[r]);
                acc[r] = fmaf(q.w, w3, acc[r]);
            }
        }
        #pragma unroll
        for (int r = 0; r < RHALF; r++)
            proj_s[r0 + r][col] = acc[r];
    }
    __syncthreads();

    // ---- Phase C: sampling coords (MROWS*32 pairs) + per-head softmax (MROWS*8) ----
    {
        #pragma unroll
        for (int i = 0; i < (MROWS * 32 + 255) / 256; i++) {
            const int o = t + i * 256;
            if (o < MROWS * 32) {
                const int row = o / 32;
                const int pair = o % 32;
                const float rx = refp[((size_t)b * NQ + n0 + row) * 2 + 0];
                const float ry = refp[((size_t)b * NQ + n0 + row) * 2 + 1];
                const float ox = tanhf(proj_s[row][pair * 2 + 0]) * RADIUS;
                const float oy = tanhf(proj_s[row][pair * 2 + 1]) * RADIUS;
                sx[row][pair] = (rx + ox) * (float)BEVW - 0.5f;
                sy[row][pair] = (ry + oy) * (float)BEVH - 0.5f;
            }
        }
        if (t < MROWS * HEADS) {   // 160
            const int row = t >> 3;
            const int h = t & 7;
            const float l0 = proj_s[row][64 + h * 4 + 0];
            const float l1 = proj_s[row][64 + h * 4 + 1];
            const float l2 = proj_s[row][64 + h * 4 + 2];
            const float l3 = proj_s[row][64 + h * 4 + 3];
            const float m = fmaxf(fmaxf(l0, l1), fmaxf(l2, l3));
            const float e0 = __expf(l0 - m);
            const float e1 = __expf(l1 - m);
            const float e2 = __expf(l2 - m);
            const float e3 = __expf(l3 - m);
            const float inv = 1.0f / (e0 + e1 + e2 + e3);
            wts[row][h * 4 + 0] = e0 * inv;
            wts[row][h * 4 + 1] = e1 * inv;
            wts[row][h * 4 + 2] = e2 * inv;
            wts[row][h * 4 + 3] = e3 * inv;
        }
    }
    __syncthreads();

    // ---- Phase D: bilinear gather. thread = (head, channel); loop over rows.
    //      Writes overwrite the (now dead) query tile in buf_s. ----
    {
        const int h = t >> 5;          // 0..7 (warp id)
        const int d = t & 31;          // 0..31
        const float* mb = memory + (size_t)b * (BEVH * BEVW) * CC + h * HD + d;
        #pragma unroll 2
        for (int r = 0; r < MROWS; r++) {
            float acc = 0.0f;
            #pragma unroll
            for (int p = 0; p < PP; p++) {
                const int pair = h * PP + p;
                const float xx = sx[r][pair];
                const float yy = sy[r][pair];
                const float x0f = floorf(xx);
                const float y0f = floorf(yy);
                const float fx = xx - x0f;
                const float fy = yy - y0f;
                const int x0 = (int)x0f;
                const int y0 = (int)y0f;
                const int x1 = x0 + 1;
                const int y1 = y0 + 1;
                const bool vx0 = (x0 >= 0) & (x0 < BEVW);
                const bool vx1 = (x1 >= 0) & (x1 < BEVW);
                const bool vy0 = (y0 >= 0) & (y0 < BEVH);
                const bool vy1 = (y1 >= 0) & (y1 < BEVH);
                const float v00 = (vx0 && vy0) ? mb[(size_t)(y0 * BEVW + x0) * CC] : 0.0f;
                const float v01 = (vx1 && vy0) ? mb[(size_t)(y0 * BEVW + x1) * CC] : 0.0f;
                const float v10 = (vx0 && vy1) ? mb[(size_t)(y1 * BEVW + x0) * CC] : 0.0f;
                const float v11 = (vx1 && vy1) ? mb[(size_t)(y1 * BEVW + x1) * CC] : 0.0f;
                const float top = v00 * (1.0f - fx) + v01 * fx;
                const float bot = v10 * (1.0f - fx) + v11 * fx;
                acc = fmaf(wts[r][pair], top * (1.0f - fy) + bot * fy, acc);
            }
            buf_s[r][h * HD + d] = acc;
        }
    }
    __syncthreads();

    // ---- Phase E: output projection. thread = column t; MROWS accumulators ----
    {
        float acc[MROWS];
        const float bo = b_out[t];
        #pragma unroll
        for (int r = 0; r < MROWS; r++) acc[r] = bo;

        const float* w = w_out + t;
        for (int k = 0; k < CC; k += 4) {
            const float w0 = w[(size_t)(k + 0) * CC];
            const float w1 = w[(size_t)(k + 1) * CC];
            const float w2 = w[(size_t)(k + 2) * CC];
            const float w3 = w[(size_t)(k + 3) * CC];
            #pragma unroll
            for (int r = 0; r < MROWS; r++) {
                const float4 f = *reinterpret_cast<const float4*>(&buf_s[r][k]);
                acc[r] = fmaf(f.x, w0, acc[r]);
                acc[r] = fmaf(f.y, w1, acc[r]);
                acc[r] = fmaf(f.z, w2, acc[r]);
                acc[r] = fmaf(f.w, w3, acc[r]);
            }
        }
        float* obase = out + ((size_t)b * NQ + n0) * CC + t;
        #pragma unroll
        for (int r = 0; r < MROWS; r++)
            obase[(size_t)r * CC] = acc[r];
    }
}

extern "C" void kernel_launch(void* const* d_in, const int* in_sizes, int n_in,
                              void* d_out, int out_size) {
    const float* query  = (const float*)d_in[0];
    const float* memory = (const float*)d_in[1];
    const float* refp   = (const float*)d_in[2];
    const float* w_off  = (const float*)d_in[3];
    const float* b_off  = (const float*)d_in[4];
    const float* w_wt   = (const float*)d_in[5];
    const float* b_wt   = (const float*)d_in[6];
    const float* w_out  = (const float*)d_in[7];
    const float* b_out  = (const float*)d_in[8];
    // d_in[9], d_in[10] = bev_h, bev_w (200x200, compiled in)

    float* out = (float*)d_out;
    deform_attn_kernel<<<BQ * GROUPS, 256>>>(query, memory, refp, w_off, b_off,
                                             w_wt, b_wt, w_out, b_out, out);
}